// round 6
// baseline (speedup 1.0000x reference)
#include <cuda_runtime.h>
#include <cstdint>

#define Tn 2048
#define Hn 256
#define Bn 256
#define Pn 24

#define NT      512       // 16 warps: jhalf = wid&1, kslot = wid>>1
#define KSLOTS  8
#define KB_PER  32                       // k-rows per k-block
#define ITS_REG 20                       // first 20 k of each block in registers
#define ITS_SM  (KB_PER - ITS_REG)       // last 12 k of each block in smem
#define WSM_ROWS (KSLOTS * ITS_SM)       // 96 rows in smem

typedef unsigned long long ull;

// Shared memory layout (float offsets)
//  Wt    : [96][256] rows (kslot*12 + i) <-> k = kslot*32 + 20 + i = 24576 floats ( 96 KB)
//  hpriv : [16][64] per-warp private h scratch {b0[32], b1[32]}    =  1024 floats (  4 KB)
//  hb    : [2][256] final h_T (written only on last iteration)     =   512 floats (  2 KB)
//  red0  : [16][256] partials buffer A                             =  4096 floats ( 16 KB)
//  red1  : [16][256] partials buffer B                             =  4096 floats ( 16 KB)
//  xs    : [2][2048] cached x rows                                 =  4096 floats ( 16 KB)
#define OFF_W    0
#define OFF_HP   24576
#define OFF_H    25600
#define OFF_RED0 26112
#define OFF_RED1 30208
#define OFF_X    34304
#define SMEM_FLOATS 38400
#define SMEM_BYTES (SMEM_FLOATS * 4)

__device__ __forceinline__ void ffma2(ull& a, ull b, ull c) {
    asm("fma.rn.f32x2 %0, %1, %2, %0;" : "+l"(a) : "l"(b), "l"(c));
}
__device__ __forceinline__ ull packf2(float lo, float hi) {
    ull r; asm("mov.b64 %0, {%1, %2};" : "=l"(r) : "f"(lo), "f"(hi)); return r;
}
__device__ __forceinline__ ull dupf2(float v) {
    ull r; asm("mov.b64 %0, {%1, %1};" : "=l"(r) : "f"(v)); return r;
}
__device__ __forceinline__ float2 u2f(ull v) {
    float2 r; asm("mov.b64 {%0, %1}, %2;" : "=f"(r.x), "=f"(r.y) : "l"(v)); return r;
}
// tanh(x) = 1 - 2/(e^{2x}+1); ex2+rcp approx, abs err ~4e-7, saturates correctly.
__device__ __forceinline__ float tanh_fast(float v) {
    float e = __expf(2.0f * v);
    return 1.0f - __fdividef(2.0f, e + 1.0f);
}

__global__ void __launch_bounds__(NT, 1)
rnn_persistent_kernel(const float* __restrict__ x,
                      const float* __restrict__ W_ih,
                      const float* __restrict__ W_hh,
                      const float* __restrict__ b_ih,
                      const float* __restrict__ b_hh,
                      const float* __restrict__ W_out,
                      const float* __restrict__ b_out,
                      float* __restrict__ out)
{
    extern __shared__ float sm[];
    float* Wt    = sm + OFF_W;
    float* hpriv = sm + OFF_HP;
    float* hb    = sm + OFF_H;
    float* xs    = sm + OFF_X;

    const int tid   = threadIdx.x;
    const int lane  = tid & 31;
    const int wid   = tid >> 5;
    const int jhalf = wid & 1;          // half of j-rows this warp covers
    const int kslot = wid >> 1;         // contiguous k-block [kslot*32, +32)
    const int kbase = kslot * KB_PER;
    const int j0    = jhalf * 128 + lane * 4;
    const int b0    = blockIdx.x * 2;
    const int fjj   = kbase + lane;     // finalize j row (own segment, both batches)

    // ---------------- init ----------------
    for (int i = tid; i < Tn; i += NT) {
        xs[i]      = x[(size_t)b0 * Tn + i];
        xs[Tn + i] = x[(size_t)(b0 + 1) * Tn + i];
    }
    // smem W rows: row r -> k = (r/ITS_SM)*32 + ITS_REG + (r%ITS_SM), transposed over j
    for (int idx = tid; idx < 256 * (WSM_ROWS / 4); idx += NT) {
        int j  = idx / (WSM_ROWS / 4);
        int rc = idx % (WSM_ROWS / 4);
        #pragma unroll
        for (int q = 0; q < 4; ++q) {
            int r = rc * 4 + q;
            int k = (r / ITS_SM) * KB_PER + ITS_REG + (r % ITS_SM);
            Wt[r * 256 + j] = W_hh[j * Hn + k];
        }
    }
    // register W: k = kbase + i, i in [0,20), packed as j-pairs for f32x2
    ull wr0[ITS_REG], wr1[ITS_REG];
    #pragma unroll
    for (int i = 0; i < ITS_REG; ++i) {
        int k = kbase + i;
        wr0[i] = packf2(W_hh[(j0 + 0) * Hn + k], W_hh[(j0 + 1) * Hn + k]);
        wr1[i] = packf2(W_hh[(j0 + 2) * Hn + k], W_hh[(j0 + 3) * Hn + k]);
    }
    const float c1 = W_ih[fjj];
    const float c0 = b_ih[fjj] + b_hh[fjj];
    // zero both red buffers (first finalize reads zeros -> h1 = tanh(xp0))
    for (int i = tid; i < 8192; i += NT) sm[OFF_RED0 + i] = 0.f;
    __syncthreads();

    float* redRead  = sm + OFF_RED0;
    float* redWrite = sm + OFF_RED1;
    float* hpw = hpriv + wid * 64;      // this warp's private h scratch

    // ---------------- recurrence ----------------
    // iteration t: finalize computes h_{t+1} from red(t) (= W*h_t) and xp[t];
    // phase B computes partials W*h_{t+1} into redWrite. ONE CTA barrier per step.
    for (int t = 0; t < Tn; ++t) {
        // ---- finalize own 32-j segment, BOTH batches (redundant with pair partner,
        //      but entirely warp-private -> no cross-warp sync needed) ----
        {
            float xv0 = xs[t];
            float xv1 = xs[Tn + t];
            float s0 = 0.f, s1 = 0.f;
            #pragma unroll
            for (int sslot = 0; sslot < KSLOTS; ++sslot) {
                s0 += redRead[(sslot * 2 + 0) * 256 + fjj];
                s1 += redRead[(sslot * 2 + 1) * 256 + fjj];
            }
            float h0 = tanh_fast(fmaf(xv0, c1, c0) + s0);
            float h1 = tanh_fast(fmaf(xv1, c1, c0) + s1);
            hpw[lane]      = h0;
            hpw[32 + lane] = h1;
            if (t == Tn - 1 && jhalf == 0) {   // publish h_T for the output head
                hb[fjj]       = h0;
                hb[256 + fjj] = h1;
            }
        }
        __syncwarp();

        // ---- phase B: partials over own k-segment, using private h scratch ----
        ull a00 = 0, a01 = 0, a10 = 0, a11 = 0;    // a{jpair}{batch}
        const float4* h0p = (const float4*)(hpw);
        const float4* h1p = (const float4*)(hpw + 32);

        #pragma unroll
        for (int blk = 0; blk < ITS_REG / 4; ++blk) {
            float4 hv0 = h0p[blk];                 // broadcast LDS.128
            float4 hv1 = h1p[blk];
            #pragma unroll
            for (int c = 0; c < 4; ++c) {
                int i = blk * 4 + c;
                ull d0 = dupf2(((const float*)&hv0)[c]);
                ull d1 = dupf2(((const float*)&hv1)[c]);
                ffma2(a00, wr0[i], d0);
                ffma2(a01, wr0[i], d1);
                ffma2(a10, wr1[i], d0);
                ffma2(a11, wr1[i], d1);
            }
        }
        const float* wp = &Wt[(kslot * ITS_SM) * 256 + j0];
        #pragma unroll
        for (int blk = 0; blk < ITS_SM / 4; ++blk) {
            float4 hv0 = h0p[ITS_REG / 4 + blk];
            float4 hv1 = h1p[ITS_REG / 4 + blk];
            #pragma unroll
            for (int c = 0; c < 4; ++c) {
                int r = blk * 4 + c;
                ulonglong2 wv = *(const ulonglong2*)(wp + r * 256);  // contiguous LDS.128
                ull d0 = dupf2(((const float*)&hv0)[c]);
                ull d1 = dupf2(((const float*)&hv1)[c]);
                ffma2(a00, wv.x, d0);
                ffma2(a01, wv.x, d1);
                ffma2(a10, wv.y, d0);
                ffma2(a11, wv.y, d1);
            }
        }

        // k-slot partials into the write buffer
        {
            float2 p00 = u2f(a00), p10 = u2f(a10);
            float2 p01 = u2f(a01), p11 = u2f(a11);
            *(float4*)&redWrite[(kslot * 2 + 0) * 256 + j0] = make_float4(p00.x, p00.y, p10.x, p10.y);
            *(float4*)&redWrite[(kslot * 2 + 1) * 256 + j0] = make_float4(p01.x, p01.y, p11.x, p11.y);
        }
        // swap buffers; single CTA-wide barrier per step
        float* tmp = redRead; redRead = redWrite; redWrite = tmp;
        __syncthreads();
    }

    // ---------------- output head ----------------
    if (tid < 2 * Pn) {
        int b = tid / Pn;
        int p = tid % Pn;
        float s = b_out[p];
        const float* wrow = &W_out[p * Hn];
        const float* hrow = &hb[b * 256];
        #pragma unroll 8
        for (int h = 0; h < Hn; ++h)
            s = fmaf(hrow[h], wrow[h], s);
        out[(size_t)(b0 + b) * Pn + p] = s;
    }
}

extern "C" void kernel_launch(void* const* d_in, const int* in_sizes, int n_in,
                              void* d_out, int out_size) {
    const float* x     = (const float*)d_in[0];
    const float* W_ih  = (const float*)d_in[1];
    const float* W_hh  = (const float*)d_in[2];
    const float* b_ih  = (const float*)d_in[3];
    const float* b_hh  = (const float*)d_in[4];
    const float* W_out = (const float*)d_in[5];
    const float* b_out = (const float*)d_in[6];
    float* out = (float*)d_out;

    cudaFuncSetAttribute(rnn_persistent_kernel,
                         cudaFuncAttributeMaxDynamicSharedMemorySize, SMEM_BYTES);
    rnn_persistent_kernel<<<Bn / 2, NT, SMEM_BYTES>>>(
        x, W_ih, W_hh, b_ih, b_hh, W_out, b_out, out);
}

// round 7
// speedup vs baseline: 1.1003x; 1.1003x over previous
#include <cuda_runtime.h>
#include <cstdint>

#define Tn 2048
#define Hn 256
#define Bn 256
#define Pn 24

#define NT      512       // 16 warps: jhalf = wid&1, kslot = wid>>1
#define KSLOTS  8
#define KB_PER  32                       // k-rows per k-block
#define ITS_REG 20                       // first 20 k of each block in registers
#define ITS_SM  (KB_PER - ITS_REG)       // last 12 k of each block in smem
#define WSM_ROWS (KSLOTS * ITS_SM)       // 96 rows in smem

// 2*log2(e): folded into W/b so tanh needs only EX2 (no pre-multiply)
#define SCALE 2.8853900817779268f

typedef unsigned long long ull;

// Shared memory layout (float offsets)
//  Wt  : [96][256] rows (kslot*12 + i) <-> k = kslot*32 + 20 + i  = 24576 floats (96 KB)
//  hb  : [2][256] batch-major hidden state                         =   512 floats ( 2 KB)
//  red : [16][256] (kslot*2 + b) partials                          =  4096 floats (16 KB)
//  xs  : [2][2048] cached x rows                                   =  4096 floats (16 KB)
#define OFF_W   0
#define OFF_H   24576
#define OFF_RED 25088
#define OFF_X   29184
#define SMEM_FLOATS 33280
#define SMEM_BYTES (SMEM_FLOATS * 4)

__device__ __forceinline__ void ffma2(ull& a, ull b, ull c) {
    asm("fma.rn.f32x2 %0, %1, %2, %0;" : "+l"(a) : "l"(b), "l"(c));
}
__device__ __forceinline__ ull packf2(float lo, float hi) {
    ull r; asm("mov.b64 %0, {%1, %2};" : "=l"(r) : "f"(lo), "f"(hi)); return r;
}
__device__ __forceinline__ ull dupf2(float v) {
    ull r; asm("mov.b64 %0, {%1, %1};" : "=l"(r) : "f"(v)); return r;
}
__device__ __forceinline__ float2 u2f(ull v) {
    float2 r; asm("mov.b64 {%0, %1}, %2;" : "=f"(r.x), "=f"(r.y) : "l"(v)); return r;
}
// tanh with pre-scaled argument: input raw = 2*log2(e)*z; returns tanh(z).
// tanh(z) = 1 - 2/(2^raw + 1). Serial chain: EX2 + ADD + RCP + FFMA (~40 cyc).
// Saturates correctly: raw->+inf => ex2->inf => rcp->0 => 1; raw->-inf => -1.
__device__ __forceinline__ float tanh_scaled(float raw) {
    float e, r;
    asm("ex2.approx.f32 %0, %1;" : "=f"(e) : "f"(raw));
    float ep1 = e + 1.0f;
    asm("rcp.approx.f32 %0, %1;" : "=f"(r) : "f"(ep1));
    return fmaf(-2.0f, r, 1.0f);
}

__global__ void __launch_bounds__(NT, 1)
rnn_persistent_kernel(const float* __restrict__ x,
                      const float* __restrict__ W_ih,
                      const float* __restrict__ W_hh,
                      const float* __restrict__ b_ih,
                      const float* __restrict__ b_hh,
                      const float* __restrict__ W_out,
                      const float* __restrict__ b_out,
                      float* __restrict__ out)
{
    extern __shared__ float sm[];
    float* Wt  = sm + OFF_W;
    float* hb  = sm + OFF_H;
    float* red = sm + OFF_RED;
    float* xs  = sm + OFF_X;

    const int tid   = threadIdx.x;
    const int lane  = tid & 31;
    const int wid   = tid >> 5;
    const int jhalf = wid & 1;          // half of j-rows this warp covers
    const int kslot = wid >> 1;         // contiguous k-block [kslot*32, +32)
    const int kbase = kslot * KB_PER;
    const int j0    = jhalf * 128 + lane * 4;
    const int b0    = blockIdx.x * 2;
    const int fb    = tid >> 8;         // finalize: batch
    const int fj    = tid & 255;        // finalize: j row

    // ---------------- init ----------------
    for (int i = tid; i < Tn; i += NT) {
        xs[i]      = x[(size_t)b0 * Tn + i];
        xs[Tn + i] = x[(size_t)(b0 + 1) * Tn + i];
    }
    // smem W rows (pre-scaled): row r -> k = (r/ITS_SM)*32 + ITS_REG + (r%ITS_SM)
    for (int idx = tid; idx < 256 * (WSM_ROWS / 4); idx += NT) {
        int j  = idx / (WSM_ROWS / 4);
        int rc = idx % (WSM_ROWS / 4);
        #pragma unroll
        for (int q = 0; q < 4; ++q) {
            int r = rc * 4 + q;
            int k = (r / ITS_SM) * KB_PER + ITS_REG + (r % ITS_SM);
            Wt[r * 256 + j] = W_hh[j * Hn + k] * SCALE;
        }
    }
    // register W (pre-scaled): k = kbase + i, i in [0,20), packed as j-pairs
    ull wr0[ITS_REG], wr1[ITS_REG];
    #pragma unroll
    for (int i = 0; i < ITS_REG; ++i) {
        int k = kbase + i;
        wr0[i] = packf2(W_hh[(j0 + 0) * Hn + k] * SCALE, W_hh[(j0 + 1) * Hn + k] * SCALE);
        wr1[i] = packf2(W_hh[(j0 + 2) * Hn + k] * SCALE, W_hh[(j0 + 3) * Hn + k] * SCALE);
    }
    const float c1 = W_ih[fj] * SCALE;
    const float c0 = (b_ih[fj] + b_hh[fj]) * SCALE;
    if (tid < 512) hb[tid] = 0.f;
    __syncthreads();

    // ---------------- recurrence ----------------
    // iteration t: phase B computes partials W*h_t; finalize makes h_{t+1}.
    for (int t = 0; t < Tn; ++t) {
        ull a00 = 0, a01 = 0, a10 = 0, a11 = 0;    // a{jpair}{batch}
        const float4* h0p = (const float4*)(hb + kbase);
        const float4* h1p = (const float4*)(hb + 256 + kbase);
        const float*  wp  = &Wt[(kslot * ITS_SM) * 256 + j0];

        // Register-W segment (fma-heavy)
        auto do_reg = [&]() {
            #pragma unroll
            for (int blk = 0; blk < ITS_REG / 4; ++blk) {
                float4 hv0 = h0p[blk];                 // broadcast LDS.128
                float4 hv1 = h1p[blk];
                #pragma unroll
                for (int c = 0; c < 4; ++c) {
                    int i = blk * 4 + c;
                    ull d0 = dupf2(((const float*)&hv0)[c]);
                    ull d1 = dupf2(((const float*)&hv1)[c]);
                    ffma2(a00, wr0[i], d0);
                    ffma2(a01, wr0[i], d1);
                    ffma2(a10, wr1[i], d0);
                    ffma2(a11, wr1[i], d1);
                }
            }
        };
        // Smem-W segment (crossbar-heavy)
        auto do_smem = [&]() {
            #pragma unroll
            for (int blk = 0; blk < ITS_SM / 4; ++blk) {
                float4 hv0 = h0p[ITS_REG / 4 + blk];
                float4 hv1 = h1p[ITS_REG / 4 + blk];
                #pragma unroll
                for (int c = 0; c < 4; ++c) {
                    int r = blk * 4 + c;
                    ulonglong2 wv = *(const ulonglong2*)(wp + r * 256);  // contiguous LDS.128
                    ull d0 = dupf2(((const float*)&hv0)[c]);
                    ull d1 = dupf2(((const float*)&hv1)[c]);
                    ffma2(a00, wv.x, d0);
                    ffma2(a01, wv.x, d1);
                    ffma2(a10, wv.y, d0);
                    ffma2(a11, wv.y, d1);
                }
            }
        };
        // Desync: half the warps hit the crossbar first, half the fma pipe first,
        // smoothing crossbar demand across the phase.
        if (jhalf == 0) { do_reg(); do_smem(); }
        else            { do_smem(); do_reg(); }

        // k-slot partials
        {
            float2 p00 = u2f(a00), p10 = u2f(a10);
            float2 p01 = u2f(a01), p11 = u2f(a11);
            *(float4*)&red[(kslot * 2 + 0) * 256 + j0] = make_float4(p00.x, p00.y, p10.x, p10.y);
            *(float4*)&red[(kslot * 2 + 1) * 256 + j0] = make_float4(p01.x, p01.y, p11.x, p11.y);
        }
        __syncthreads();

        // finalize: thread (fb, fj) reduces its 8 k-slot partials
        {
            float r0 = red[(0 * 2 + fb) * 256 + fj];
            float r1 = red[(1 * 2 + fb) * 256 + fj];
            float r2 = red[(2 * 2 + fb) * 256 + fj];
            float r3 = red[(3 * 2 + fb) * 256 + fj];
            float r4 = red[(4 * 2 + fb) * 256 + fj];
            float r5 = red[(5 * 2 + fb) * 256 + fj];
            float r6 = red[(6 * 2 + fb) * 256 + fj];
            float r7 = red[(7 * 2 + fb) * 256 + fj];
            float s  = ((r0 + r1) + (r2 + r3)) + ((r4 + r5) + (r6 + r7));
            float xv = xs[fb * Tn + t];
            float h  = tanh_scaled(fmaf(xv, c1, c0) + s);
            hb[fb * 256 + fj] = h;   // contiguous store, 1 wavefront
        }
        __syncthreads();
    }

    // ---------------- output head ----------------
    if (tid < 2 * Pn) {
        int b = tid / Pn;
        int p = tid % Pn;
        float s = b_out[p];
        const float* wrow = &W_out[p * Hn];
        const float* hrow = &hb[b * 256];
        #pragma unroll 8
        for (int h = 0; h < Hn; ++h)
            s = fmaf(hrow[h], wrow[h], s);
        out[(size_t)(b0 + b) * Pn + p] = s;
    }
}

extern "C" void kernel_launch(void* const* d_in, const int* in_sizes, int n_in,
                              void* d_out, int out_size) {
    const float* x     = (const float*)d_in[0];
    const float* W_ih  = (const float*)d_in[1];
    const float* W_hh  = (const float*)d_in[2];
    const float* b_ih  = (const float*)d_in[3];
    const float* b_hh  = (const float*)d_in[4];
    const float* W_out = (const float*)d_in[5];
    const float* b_out = (const float*)d_in[6];
    float* out = (float*)d_out;

    cudaFuncSetAttribute(rnn_persistent_kernel,
                         cudaFuncAttributeMaxDynamicSharedMemorySize, SMEM_BYTES);
    rnn_persistent_kernel<<<Bn / 2, NT, SMEM_BYTES>>>(
        x, W_ih, W_hh, b_ih, b_hh, W_out, b_out, out);
}